// round 16
// baseline (speedup 1.0000x reference)
#include <cuda_runtime.h>

// Problem constants (fixed by the reference: x=(128,128,16,16) f32, logits=(128,100))
#define B_  128
#define D_  32768          // C*H*W
#define D4_ (D_/4)         // 8192 float4 per prototype row
#define K_  100
#define TILE_ 10           // class tile width (j); diag tiles split 5+5 in i
#define NCHUNK_ 32         // d4 chunks of 256
#define NNOND_  (NCHUNK_ * 90)            // 2880 non-diagonal full tiles
#define NDIAGH_ (NCHUNK_ * TILE_ * 2)     // 640 diagonal half tiles
#define NBLOCKS_ (NNOND_ + NDIAGH_)       // 3520
#define NCONC_  592                       // 148 SM x 4 blocks (wave-0 size)

// Scratch (allocation-free rule: __device__ globals)
__device__ int   g_items[B_];    // CSR items: batch indices grouped by class, ascending
__device__ int   g_off[K_ + 1];  // CSR offsets
__device__ float g_inv[K_];      // 1/count (0 if count==0)

// ---------------------------------------------------------------------------
// Kernel 1: argmax per batch row + deterministic CSR build (single block).
// softmax monotone -> argmax(probs) == argmax(logits); strict > + ascending
// scan + (value,index) shuffle reduce matches jnp.argmax tie-breaking.
// CSR: counts via smem atomics (order-independent), serial smem prefix,
// stable rank scan -> bitwise-deterministic. PDL trigger at the end.
// NOTE (R5/R14 post-mortems): fusing this into the big kernel is
// structurally worse — the serial Phase-A chain at every block start drains
// the store stream (DRAM 82% -> 70%). Keep the 2-kernel PDL pipeline.
// ---------------------------------------------------------------------------
__global__ __launch_bounds__(1024) void argmax_csr_kernel(
        const float* __restrict__ logits) {
    __shared__ int s_cls[B_];
    __shared__ int s_cnt[K_];
    __shared__ int s_off[K_ + 1];

    int tid = threadIdx.x;        // 0..1023
    int b   = tid >> 3;           // row 0..127
    int sub = tid & 7;            // 0..7 within row

    if (tid < K_) s_cnt[tid] = 0;

    const float* row = logits + (size_t)b * K_;
    float v   = row[sub];
    int   idx = sub;
    #pragma unroll
    for (int k = sub + 8; k < K_; k += 8) {
        float t = row[k];
        if (t > v) { v = t; idx = k; }   // ascending + strict > => lowest index kept
    }
    #pragma unroll
    for (int off = 4; off > 0; off >>= 1) {
        float ov = __shfl_down_sync(0xffffffffu, v,   off, 8);
        int   oi = __shfl_down_sync(0xffffffffu, idx, off, 8);
        if (ov > v || (ov == v && oi < idx)) { v = ov; idx = oi; }
    }
    __syncthreads();              // counts zeroed before atomics
    if (sub == 0) {
        s_cls[b] = idx;
        atomicAdd(&s_cnt[idx], 1);
    }
    __syncthreads();

    if (tid == 0) {
        int off = 0;
        #pragma unroll 4
        for (int k = 0; k < K_; k++) { s_off[k] = off; off += s_cnt[k]; }
        s_off[K_] = off;
    }
    __syncthreads();

    if (tid < B_) {
        int myc = s_cls[tid];
        int rank = 0;
        #pragma unroll 8
        for (int bb = 0; bb < B_; bb++)
            rank += (bb < tid && s_cls[bb] == myc) ? 1 : 0;
        g_items[s_off[myc] + rank] = tid;
    }

    if (tid < K_) {
        g_off[tid] = s_off[tid];
        int c = s_cnt[tid];
        g_inv[tid] = (c > 0) ? (1.0f / (float)c) : 0.0f;
    }
    if (tid == 0) g_off[K_] = s_off[K_];

    cudaTriggerProgrammaticLaunchCompletion();
}

// ---------------------------------------------------------------------------
// Tile worker: fully specialized at compile time. ILO/ICNT/DIAG are template
// constants -> every pj[] index is a constant after unroll (NO dynamic
// register indexing, the R9/R10 local-spill trap).
// ---------------------------------------------------------------------------
template <int ILO, int ICNT, bool DIAG>
__device__ __forceinline__ void process_tile(
        int i0, int j0, int d4,
        const int* s_off, const int* s_items, const float* s_inv,
        const float4* __restrict__ x4,
        float4* __restrict__ proto4,
        float4* __restrict__ out4) {
    // prototype rows j0..j0+9 (registers for the whole tile)
    float4 pj[TILE_];
    #pragma unroll
    for (int jj = 0; jj < TILE_; jj++) {
        const int k = j0 + jj;
        float4 acc = make_float4(0.f, 0.f, 0.f, 0.f);
        const int s = s_off[k], e = s_off[k + 1];
        for (int u = s; u < e; u++) {
            float4 v = x4[(size_t)s_items[u] * D4_ + d4];
            acc.x += v.x; acc.y += v.y; acc.z += v.z; acc.w += v.w;
        }
        const float inv = s_inv[k];  // count==0 -> acc==0, inv==0 -> 0 (matches where())
        acc.x *= inv; acc.y *= inv; acc.z *= inv; acc.w *= inv;
        pj[jj] = acc;
    }

    // first diag half publishes the prototype output (once per (row, d4))
    if (DIAG && ILO == 0) {
        #pragma unroll
        for (int jj = 0; jj < TILE_; jj++)
            __stcs(&proto4[(size_t)(j0 + jj) * D4_ + d4], pj[jj]);
    }

    #pragma unroll
    for (int ii = 0; ii < ICNT; ii++) {
        const int k = i0 + ILO + ii;
        float4 pi;
        if (DIAG) {
            pi = pj[ILO + ii];            // compile-time constant index
        } else {
            float4 acc = make_float4(0.f, 0.f, 0.f, 0.f);
            const int s = s_off[k], e = s_off[k + 1];
            for (int u = s; u < e; u++) {
                float4 v = x4[(size_t)s_items[u] * D4_ + d4];
                acc.x += v.x; acc.y += v.y; acc.z += v.z; acc.w += v.w;
            }
            const float inv = s_inv[k];
            acc.x *= inv; acc.y *= inv; acc.z *= inv; acc.w *= inv;
            pi = acc;
        }
        #pragma unroll
        for (int jj = 0; jj < TILE_; jj++) {
            float4 r;
            r.x = pj[jj].x - pi.x;
            r.y = pj[jj].y - pi.y;
            r.z = pj[jj].z - pi.z;
            r.w = pj[jj].w - pi.w;
            __stcs(&out4[(size_t)(k * K_ + (j0 + jj)) * D4_ + d4], r);
        }
    }
}

// ---------------------------------------------------------------------------
// Kernel 2 (fused): prototypes + inter-class matrix.
// 2880 full non-diag tiles (10x10) run first; the 320 diagonal tiles run
// LAST as 640 template-specialized half tiles (5 i-rows, ILO 0/5) -> the
// dispatch tail is ~half-duration blocks: mixed schedule lands within ~1%
// of the work/592 ideal (wave quantization solved). pj[10] register-
// resident, x (16 MB) + CSR L2-resident, __stcs on the 1.33 GB write stream
// (never re-read). DRAM-write-bound at ~6.5 TB/s.
//
// NEW: PDL pre-sync prefetch. Wave-0 blocks (bid < 592) prefetch their
// entire x slice (4096 cache lines, 16 dedup'd lines/thread) into L2
// BEFORE cudaGridDependencySynchronize — x is a harness input, independent
// of kernel 1, so this is safe and runs concurrently with the argmax
// kernel. The 16 MB cold x read overlaps the ~4us argmax node instead of
// serializing after it; wave-0's pj loop then hits L2.
// ---------------------------------------------------------------------------
__global__ __launch_bounds__(256, 4) void inter_fused_kernel(
        const float4* __restrict__ x4,
        float4* __restrict__ proto4,
        float4* __restrict__ out4) {
    __shared__ int   s_off[K_ + 1];
    __shared__ int   s_items[B_];
    __shared__ float s_inv[K_];

    const int t   = threadIdx.x;
    const int bid = blockIdx.x;

    // ---- pre-sync: overlap with argmax kernel (PDL) ----
    if (bid < NCONC_) {
        // wave-0: prefetch this block's x slice (chunk = bid % 32, since
        // NCONC_ < NNOND_ and non-diag mapping is chunk-fastest).
        const int chunk = bid % NCHUNK_;
        const char* xb = (const char*)x4 + (size_t)chunk * 4096;
        #pragma unroll
        for (int i = 0; i < 16; i++) {
            const int l   = t * 16 + i;        // 0..4095 lines
            const int row = l >> 5;            // batch row 0..127
            const int jo  = l & 31;            // 128B line within the 4KB slice
            const char* p = xb + (size_t)row * (D_ * 4) + jo * 128;
            asm volatile("prefetch.global.L2 [%0];" :: "l"(p));
        }
    }

    // Wait for argmax_csr_kernel's g_* publishes (PDL dependency).
    cudaGridDependencySynchronize();

    if (t < K_ + 1) s_off[t]   = g_off[t];
    if (t < B_)     s_items[t] = g_items[t];
    if (t < K_)     s_inv[t]   = g_inv[t];
    __syncthreads();

    if (bid < NNOND_) {
        // non-diagonal full tiles (chunk fastest)
        const int chunk = bid % NCHUNK_;
        const int q   = bid / NCHUNK_;    // 0..89
        const int r   = q / 9;            // tile row 0..9
        const int c9  = q % 9;
        const int c   = c9 + (c9 >= r ? 1 : 0);   // skip diagonal column
        process_tile<0, TILE_, false>(r * TILE_, c * TILE_, chunk * 256 + t,
                                      s_off, s_items, s_inv, x4, proto4, out4);
    } else {
        // diagonal half tiles, dispatched last
        const int m     = bid - NNOND_;   // 0..639
        const int chunk = m % NCHUNK_;
        const int q     = m / NCHUNK_;    // 0..19
        const int dq    = q >> 1;         // diag tile 0..9
        const int i0    = dq * TILE_;
        const int d4    = chunk * 256 + t;
        if ((q & 1) == 0)
            process_tile<0, TILE_ / 2, true>(i0, i0, d4, s_off, s_items, s_inv,
                                             x4, proto4, out4);
        else
            process_tile<TILE_ / 2, TILE_ / 2, true>(i0, i0, d4, s_off, s_items,
                                                     s_inv, x4, proto4, out4);
    }
}

// ---------------------------------------------------------------------------
// Launcher. Output layout: [prototypes (100*32768 f32) | inter (100*100*32768 f32)]
// ---------------------------------------------------------------------------
extern "C" void kernel_launch(void* const* d_in, const int* in_sizes, int n_in,
                              void* d_out, int out_size) {
    const float* x      = (const float*)d_in[0];   // (128,128,16,16) f32
    const float* logits = (const float*)d_in[1];   // (128,100) f32
    float* out = (float*)d_out;

    const float4* x4     = (const float4*)x;
    float4*       proto4 = (float4*)out;                       // first 819200 float4
    float4*       inter4 = (float4*)out + (size_t)K_ * D4_;    // rest

    argmax_csr_kernel<<<1, 1024>>>(logits);

    cudaLaunchConfig_t cfg = {};
    cfg.gridDim  = dim3(NBLOCKS_);   // 3520: 2880 full non-diag + 640 diag halves
    cfg.blockDim = dim3(256);
    cfg.dynamicSmemBytes = 0;
    cfg.stream = 0;
    cudaLaunchAttribute attrs[1];
    attrs[0].id = cudaLaunchAttributeProgrammaticStreamSerialization;
    attrs[0].val.programmaticStreamSerializationAllowed = 1;
    cfg.attrs = attrs;
    cfg.numAttrs = 1;
    cudaLaunchKernelEx(&cfg, inter_fused_kernel, x4, proto4, inter4);
}

// round 17
// speedup vs baseline: 1.0429x; 1.0429x over previous
#include <cuda_runtime.h>

// Problem constants (fixed by the reference: x=(128,128,16,16) f32, logits=(128,100))
#define B_  128
#define D_  32768          // C*H*W
#define D4_ (D_/4)         // 8192 float4 per prototype row
#define K_  100
#define TILE_ 10           // class tile width (j); diag tiles split 5+5 in i
#define NCHUNK_ 32         // d4 chunks of 256
#define NNOND_  (NCHUNK_ * 90)            // 2880 non-diagonal full tiles
#define NDIAGH_ (NCHUNK_ * TILE_ * 2)     // 640 diagonal half tiles
#define NBLOCKS_ (NNOND_ + NDIAGH_)       // 3520

// Scratch (allocation-free rule: __device__ globals)
__device__ int   g_items[B_];    // CSR items: batch indices grouped by class, ascending
__device__ int   g_off[K_ + 1];  // CSR offsets
__device__ float g_inv[K_];      // 1/count (0 if count==0)

// ---------------------------------------------------------------------------
// Kernel 1: argmax per batch row + deterministic CSR build (single block).
// softmax monotone -> argmax(probs) == argmax(logits); strict > + ascending
// scan + (value,index) shuffle reduce matches jnp.argmax tie-breaking.
// CSR: counts via smem atomics (order-independent), serial smem prefix,
// stable rank scan -> bitwise-deterministic. PDL trigger at the end.
// Session post-mortems (final): fusing this into kernel 2 (R5/R14) drains
// the store stream at every block start (DRAM 82%->70%); pre-sync L2
// prefetch of x (R16) adds LSU pressure and regresses. The 2-kernel PDL
// pipeline below is the empirical optimum.
// ---------------------------------------------------------------------------
__global__ __launch_bounds__(1024) void argmax_csr_kernel(
        const float* __restrict__ logits) {
    __shared__ int s_cls[B_];
    __shared__ int s_cnt[K_];
    __shared__ int s_off[K_ + 1];

    int tid = threadIdx.x;        // 0..1023
    int b   = tid >> 3;           // row 0..127
    int sub = tid & 7;            // 0..7 within row

    if (tid < K_) s_cnt[tid] = 0;

    const float* row = logits + (size_t)b * K_;
    float v   = row[sub];
    int   idx = sub;
    #pragma unroll
    for (int k = sub + 8; k < K_; k += 8) {
        float t = row[k];
        if (t > v) { v = t; idx = k; }   // ascending + strict > => lowest index kept
    }
    #pragma unroll
    for (int off = 4; off > 0; off >>= 1) {
        float ov = __shfl_down_sync(0xffffffffu, v,   off, 8);
        int   oi = __shfl_down_sync(0xffffffffu, idx, off, 8);
        if (ov > v || (ov == v && oi < idx)) { v = ov; idx = oi; }
    }
    __syncthreads();              // counts zeroed before atomics
    if (sub == 0) {
        s_cls[b] = idx;
        atomicAdd(&s_cnt[idx], 1);
    }
    __syncthreads();

    if (tid == 0) {
        int off = 0;
        #pragma unroll 4
        for (int k = 0; k < K_; k++) { s_off[k] = off; off += s_cnt[k]; }
        s_off[K_] = off;
    }
    __syncthreads();

    if (tid < B_) {
        int myc = s_cls[tid];
        int rank = 0;
        #pragma unroll 8
        for (int bb = 0; bb < B_; bb++)
            rank += (bb < tid && s_cls[bb] == myc) ? 1 : 0;
        g_items[s_off[myc] + rank] = tid;
    }

    if (tid < K_) {
        g_off[tid] = s_off[tid];
        int c = s_cnt[tid];
        g_inv[tid] = (c > 0) ? (1.0f / (float)c) : 0.0f;
    }
    if (tid == 0) g_off[K_] = s_off[K_];

    cudaTriggerProgrammaticLaunchCompletion();
}

// ---------------------------------------------------------------------------
// Tile worker: fully specialized at compile time. ILO/ICNT/DIAG are template
// constants -> every pj[] index is a constant after unroll (NO dynamic
// register indexing, the R9/R10 local-spill trap).
// ---------------------------------------------------------------------------
template <int ILO, int ICNT, bool DIAG>
__device__ __forceinline__ void process_tile(
        int i0, int j0, int d4,
        const int* s_off, const int* s_items, const float* s_inv,
        const float4* __restrict__ x4,
        float4* __restrict__ proto4,
        float4* __restrict__ out4) {
    // prototype rows j0..j0+9 (registers for the whole tile)
    float4 pj[TILE_];
    #pragma unroll
    for (int jj = 0; jj < TILE_; jj++) {
        const int k = j0 + jj;
        float4 acc = make_float4(0.f, 0.f, 0.f, 0.f);
        const int s = s_off[k], e = s_off[k + 1];
        for (int u = s; u < e; u++) {
            float4 v = x4[(size_t)s_items[u] * D4_ + d4];
            acc.x += v.x; acc.y += v.y; acc.z += v.z; acc.w += v.w;
        }
        const float inv = s_inv[k];  // count==0 -> acc==0, inv==0 -> 0 (matches where())
        acc.x *= inv; acc.y *= inv; acc.z *= inv; acc.w *= inv;
        pj[jj] = acc;
    }

    // first diag half publishes the prototype output (once per (row, d4))
    if (DIAG && ILO == 0) {
        #pragma unroll
        for (int jj = 0; jj < TILE_; jj++)
            __stcs(&proto4[(size_t)(j0 + jj) * D4_ + d4], pj[jj]);
    }

    #pragma unroll
    for (int ii = 0; ii < ICNT; ii++) {
        const int k = i0 + ILO + ii;
        float4 pi;
        if (DIAG) {
            pi = pj[ILO + ii];            // compile-time constant index
        } else {
            float4 acc = make_float4(0.f, 0.f, 0.f, 0.f);
            const int s = s_off[k], e = s_off[k + 1];
            for (int u = s; u < e; u++) {
                float4 v = x4[(size_t)s_items[u] * D4_ + d4];
                acc.x += v.x; acc.y += v.y; acc.z += v.z; acc.w += v.w;
            }
            const float inv = s_inv[k];
            acc.x *= inv; acc.y *= inv; acc.z *= inv; acc.w *= inv;
            pi = acc;
        }
        #pragma unroll
        for (int jj = 0; jj < TILE_; jj++) {
            float4 r;
            r.x = pj[jj].x - pi.x;
            r.y = pj[jj].y - pi.y;
            r.z = pj[jj].z - pi.z;
            r.w = pj[jj].w - pi.w;
            __stcs(&out4[(size_t)(k * K_ + (j0 + jj)) * D4_ + d4], r);
        }
    }
}

// ---------------------------------------------------------------------------
// Kernel 2 (fused): prototypes + inter-class matrix.
// 2880 full non-diag tiles (10x10) run first; the 320 diagonal tiles run
// LAST as 640 template-specialized half tiles (5 i-rows, ILO 0/5) -> the
// dispatch tail is ~half-duration blocks: mixed schedule lands within ~1%
// of the work/592 ideal (wave quantization solved). pj[10] register-
// resident, x (16 MB) + CSR L2-resident, __stcs on the 1.33 GB write stream
// (never re-read). DRAM-write-bound at ~6.5 TB/s (the measured ceiling for
// this access pattern). PDL overlaps this launch with kernel 1.
// ---------------------------------------------------------------------------
__global__ __launch_bounds__(256, 4) void inter_fused_kernel(
        const float4* __restrict__ x4,
        float4* __restrict__ proto4,
        float4* __restrict__ out4) {
    __shared__ int   s_off[K_ + 1];
    __shared__ int   s_items[B_];
    __shared__ float s_inv[K_];

    // Wait for argmax_csr_kernel's g_* publishes (PDL dependency).
    cudaGridDependencySynchronize();

    const int t = threadIdx.x;
    if (t < K_ + 1) s_off[t]   = g_off[t];
    if (t < B_)     s_items[t] = g_items[t];
    if (t < K_)     s_inv[t]   = g_inv[t];
    __syncthreads();

    const int bid = blockIdx.x;
    if (bid < NNOND_) {
        // non-diagonal full tiles (chunk fastest)
        const int chunk = bid % NCHUNK_;
        const int q   = bid / NCHUNK_;    // 0..89
        const int r   = q / 9;            // tile row 0..9
        const int c9  = q % 9;
        const int c   = c9 + (c9 >= r ? 1 : 0);   // skip diagonal column
        process_tile<0, TILE_, false>(r * TILE_, c * TILE_, chunk * 256 + t,
                                      s_off, s_items, s_inv, x4, proto4, out4);
    } else {
        // diagonal half tiles, dispatched last
        const int m     = bid - NNOND_;   // 0..639
        const int chunk = m % NCHUNK_;
        const int q     = m / NCHUNK_;    // 0..19
        const int dq    = q >> 1;         // diag tile 0..9
        const int i0    = dq * TILE_;
        const int d4    = chunk * 256 + t;
        if ((q & 1) == 0)
            process_tile<0, TILE_ / 2, true>(i0, i0, d4, s_off, s_items, s_inv,
                                             x4, proto4, out4);
        else
            process_tile<TILE_ / 2, TILE_ / 2, true>(i0, i0, d4, s_off, s_items,
                                                     s_inv, x4, proto4, out4);
    }
}

// ---------------------------------------------------------------------------
// Launcher. Output layout: [prototypes (100*32768 f32) | inter (100*100*32768 f32)]
// ---------------------------------------------------------------------------
extern "C" void kernel_launch(void* const* d_in, const int* in_sizes, int n_in,
                              void* d_out, int out_size) {
    const float* x      = (const float*)d_in[0];   // (128,128,16,16) f32
    const float* logits = (const float*)d_in[1];   // (128,100) f32
    float* out = (float*)d_out;

    const float4* x4     = (const float4*)x;
    float4*       proto4 = (float4*)out;                       // first 819200 float4
    float4*       inter4 = (float4*)out + (size_t)K_ * D4_;    // rest

    argmax_csr_kernel<<<1, 1024>>>(logits);

    cudaLaunchConfig_t cfg = {};
    cfg.gridDim  = dim3(NBLOCKS_);   // 3520: 2880 full non-diag + 640 diag halves
    cfg.blockDim = dim3(256);
    cfg.dynamicSmemBytes = 0;
    cfg.stream = 0;
    cudaLaunchAttribute attrs[1];
    attrs[0].id = cudaLaunchAttributeProgrammaticStreamSerialization;
    attrs[0].val.programmaticStreamSerializationAllowed = 1;
    cfg.attrs = attrs;
    cfg.numAttrs = 1;
    cudaLaunchKernelEx(&cfg, inter_fused_kernel, x4, proto4, inter4);
}